// round 1
// baseline (speedup 1.0000x reference)
#include <cuda_runtime.h>

#define NN 50000
#define NE 600000
#define DD 128
#define NL 5

// ---------------- scratch (no allocations allowed) ----------------
__device__ int   g_is64;
__device__ int   g_deg[NN];
__device__ int   g_cursor[NN];
__device__ int   g_rowptr[NN + 1];
__device__ int   g_col[NE];
__device__ float g_h0[NN * DD];
__device__ float g_h1[NN * DD];
__device__ float g_z[NN * DD];

// ---------------- dtype detection for edge_index ----------------
// If int64 (little endian, values < 50000) every odd 32-bit word is 0.
// If int32, odd words are random indices (virtually never all zero).
__global__ void detect_kernel(const int* __restrict__ p) {
    if (threadIdx.x == 0) {
        int acc = 0;
#pragma unroll
        for (int i = 0; i < 64; i++) acc |= p[2 * i + 1];
        g_is64 = (acc == 0) ? 1 : 0;
    }
}

__device__ __forceinline__ int edge_at(const int* __restrict__ p, int idx) {
    return g_is64 ? p[2 * idx] : p[idx];
}

// ---------------- CSR build ----------------
__global__ void zero_kernel() {
    int i = blockIdx.x * blockDim.x + threadIdx.x;
    if (i < NN) { g_deg[i] = 0; g_cursor[i] = 0; }
}

__global__ void hist_kernel(const int* __restrict__ ei) {
    int e = blockIdx.x * blockDim.x + threadIdx.x;
    if (e < NE) {
        int dst = edge_at(ei, NE + e);
        atomicAdd(&g_deg[dst], 1);
    }
}

__global__ void scan_kernel() {
    __shared__ int ssum[1024];
    __shared__ int scarry;
    int tid = threadIdx.x;
    if (tid == 0) scarry = 0;
    __syncthreads();
    for (int base = 0; base < NN; base += 8192) {
        int v[8];
        int loc = 0;
#pragma unroll
        for (int q = 0; q < 8; q++) {
            int i = base + tid * 8 + q;
            int x = (i < NN) ? g_deg[i] : 0;
            loc += x;
            v[q] = loc;
        }
        ssum[tid] = loc;
        __syncthreads();
        for (int off = 1; off < 1024; off <<= 1) {
            int t = (tid >= off) ? ssum[tid - off] : 0;
            __syncthreads();
            ssum[tid] += t;
            __syncthreads();
        }
        int excl = ssum[tid] - loc;
        int tot = ssum[1023];
        int c = scarry;
#pragma unroll
        for (int q = 0; q < 8; q++) {
            int i = base + tid * 8 + q;
            if (i < NN) g_rowptr[i + 1] = c + excl + v[q];
        }
        __syncthreads();
        if (tid == 0) scarry = c + tot;
        __syncthreads();
    }
    if (tid == 0) g_rowptr[0] = 0;
}

__global__ void fill_kernel(const int* __restrict__ ei) {
    int e = blockIdx.x * blockDim.x + threadIdx.x;
    if (e < NE) {
        int src = edge_at(ei, e);
        int dst = edge_at(ei, NE + e);
        int pos = g_rowptr[dst] + atomicAdd(&g_cursor[dst], 1);
        g_col[pos] = src;
    }
}

// ---------------- per-layer: z = h + sum_{src->n} h[src] ----------------
// one warp per node; each lane owns 4 floats (float4) of the 128-wide row
__global__ __launch_bounds__(256) void aggregate_kernel(const float* __restrict__ hin) {
    int warp = (blockIdx.x * blockDim.x + threadIdx.x) >> 5;
    int lane = threadIdx.x & 31;
    if (warp >= NN) return;
    const float4* hv = (const float4*)hin;
    float4 acc = __ldg(&hv[warp * 32 + lane]);   // (1+eps)*h with eps=0
    int beg = g_rowptr[warp];
    int end = g_rowptr[warp + 1];
    for (int e = beg; e < end; e++) {
        int s = __ldg(&g_col[e]);
        float4 v = __ldg(&hv[s * 32 + lane]);
        acc.x += v.x; acc.y += v.y; acc.z += v.z; acc.w += v.w;
    }
    ((float4*)g_z)[warp * 32 + lane] = acc;
}

// ---------------- per-layer fused MLP ----------------
// out = [leaky] ( leaky(z @ W1 + b1) @ W2 + b2 )
// 32-node tile per block, 256 threads.
__global__ __launch_bounds__(256) void mlp_kernel(
    const float* __restrict__ W1, const float* __restrict__ b1,
    const float* __restrict__ W2, const float* __restrict__ b2,
    float* __restrict__ out, int do_relu)
{
    __shared__ float zs[32][128];   // 16 KB
    __shared__ float ys[32][256];   // 32 KB  (total 48 KB exactly)
    int tid = threadIdx.x;
    int row0 = blockIdx.x * 32;

    // load z tile (vectorized, coalesced)
    {
        const float4* zv = (const float4*)g_z;
        float4* zsv = (float4*)zs;
        for (int t = tid; t < 32 * 32; t += 256) {
            int r = t >> 5;
            int gr = row0 + r;
            float4 val = make_float4(0.f, 0.f, 0.f, 0.f);
            if (gr < NN) val = __ldg(&zv[gr * 32 + (t & 31)]);
            zsv[t] = val;
        }
    }
    __syncthreads();

    // phase 1: hidden = leaky(z @ W1 + b1), thread j owns hidden column j
    {
        int j = tid;
        float acc[32];
#pragma unroll
        for (int i = 0; i < 32; i++) acc[i] = 0.f;
        const float* w = W1 + j;
#pragma unroll 4
        for (int k = 0; k < 128; k++) {
            float wv = __ldg(&w[k * 256]);       // coalesced across j
#pragma unroll
            for (int i = 0; i < 32; i++) acc[i] += zs[i][k] * wv;  // broadcast LDS
        }
        float bj = __ldg(&b1[j]);
#pragma unroll
        for (int i = 0; i < 32; i++) {
            float v = acc[i] + bj;
            v = (v > 0.f) ? v : 0.2f * v;
            ys[i][j] = v;                        // conflict-free (consecutive j)
        }
    }
    __syncthreads();

    // phase 2: out = hidden @ W2 + b2 ; thread t -> (col c, 16-row half h)
    {
        int c = tid & 127;
        int h = tid >> 7;
        float acc[16];
#pragma unroll
        for (int i = 0; i < 16; i++) acc[i] = 0.f;
        const float* w = W2 + c;
#pragma unroll 2
        for (int k = 0; k < 256; k++) {
            float wv = __ldg(&w[k * 128]);       // coalesced across c
#pragma unroll
            for (int i = 0; i < 16; i++) acc[i] += ys[h * 16 + i][k] * wv;  // broadcast
        }
        float bc = __ldg(&b2[c]);
#pragma unroll
        for (int i = 0; i < 16; i++) {
            int r = row0 + h * 16 + i;
            if (r < NN) {
                float v = acc[i] + bc;
                if (do_relu) v = (v > 0.f) ? v : 0.2f * v;
                out[r * DD + c] = v;
            }
        }
    }
}

// ---------------- launch ----------------
extern "C" void kernel_launch(void* const* d_in, const int* in_sizes, int n_in,
                              void* d_out, int out_size) {
    const float* x  = (const float*)d_in[0];
    const int*   ei = (const int*)d_in[1];
    const float* W1 = (const float*)d_in[2];
    const float* b1 = (const float*)d_in[3];
    const float* W2 = (const float*)d_in[4];
    const float* b2 = (const float*)d_in[5];
    float* out = (float*)d_out;

    float *h0p, *h1p;
    cudaGetSymbolAddress((void**)&h0p, g_h0);
    cudaGetSymbolAddress((void**)&h1p, g_h1);

    detect_kernel<<<1, 32>>>(ei);
    zero_kernel<<<(NN + 1023) / 1024, 1024>>>();
    hist_kernel<<<(NE + 255) / 256, 256>>>(ei);
    scan_kernel<<<1, 1024>>>();
    fill_kernel<<<(NE + 255) / 256, 256>>>(ei);

    const float* hin = x;
    float* bufs[2] = { h0p, h1p };
    for (int l = 0; l < NL; l++) {
        aggregate_kernel<<<(NN * 32 + 255) / 256, 256>>>(hin);
        float* ho = (l == NL - 1) ? out : bufs[l & 1];
        mlp_kernel<<<(NN + 31) / 32, 256>>>(
            W1 + (size_t)l * DD * 2 * DD,
            b1 + (size_t)l * 2 * DD,
            W2 + (size_t)l * 2 * DD * DD,
            b2 + (size_t)l * DD,
            ho, (l < NL - 1) ? 1 : 0);
        hin = ho;
    }
}

// round 3
// speedup vs baseline: 1.7477x; 1.7477x over previous
#include <cuda_runtime.h>
#include <cuda_bf16.h>
#include <cstdint>

#define NN 50000
#define NE 600000
#define DD 128
#define NL 5

// ---------------- scratch ----------------
__device__ int   g_is64;
__device__ int   g_deg[NN];
__device__ int   g_cursor[NN];
__device__ int   g_rowptr[NN + 1];
__device__ int   g_col[NE];
__device__ float g_h0[NN * DD];
__device__ float g_h1[NN * DD];
__device__ float g_z[NN * DD];

// split-bf16 weights, transposed: w1 as [L][256 n][128 k], w2 as [L][128 n][256 k]
__device__ __nv_bfloat16 g_w1h[NL * 256 * 128];
__device__ __nv_bfloat16 g_w1l[NL * 256 * 128];
__device__ __nv_bfloat16 g_w2h[NL * 128 * 256];
__device__ __nv_bfloat16 g_w2l[NL * 128 * 256];

#define STILE 1024
#define NTILE ((NN + STILE - 1) / STILE)
__device__ int g_tsum[NTILE];

// ---------------- helpers ----------------
__device__ __forceinline__ float leaky(float v) { return v > 0.f ? v : 0.2f * v; }

__device__ __forceinline__ void split2(float a, float b, uint32_t& hw, uint32_t& lw) {
    __nv_bfloat16 ha = __float2bfloat16(a);
    __nv_bfloat16 hb = __float2bfloat16(b);
    float ra = a - __bfloat162float(ha);
    float rb = b - __bfloat162float(hb);
    __nv_bfloat16 la = __float2bfloat16(ra);
    __nv_bfloat16 lb = __float2bfloat16(rb);
    hw = (uint32_t)__bfloat16_as_ushort(ha) | ((uint32_t)__bfloat16_as_ushort(hb) << 16);
    lw = (uint32_t)__bfloat16_as_ushort(la) | ((uint32_t)__bfloat16_as_ushort(lb) << 16);
}

__device__ __forceinline__ void mma16816(float* d, const uint32_t* a, const uint32_t* b) {
    asm volatile(
        "mma.sync.aligned.m16n8k16.row.col.f32.bf16.bf16.f32 "
        "{%0,%1,%2,%3}, {%4,%5,%6,%7}, {%8,%9}, {%0,%1,%2,%3};"
        : "+f"(d[0]), "+f"(d[1]), "+f"(d[2]), "+f"(d[3])
        : "r"(a[0]), "r"(a[1]), "r"(a[2]), "r"(a[3]), "r"(b[0]), "r"(b[1]));
}

// ---------------- dtype detect ----------------
__global__ void detect_kernel(const int* __restrict__ p) {
    if (threadIdx.x == 0) {
        int acc = 0;
#pragma unroll
        for (int i = 0; i < 64; i++) acc |= p[2 * i + 1];
        g_is64 = (acc == 0) ? 1 : 0;
    }
}
__device__ __forceinline__ int edge_at(const int* __restrict__ p, int idx) {
    return g_is64 ? p[2 * idx] : p[idx];
}

// ---------------- CSR build ----------------
__global__ void zero_kernel() {
    int i = blockIdx.x * blockDim.x + threadIdx.x;
    if (i < NN) { g_deg[i] = 0; g_cursor[i] = 0; }
}
__global__ void hist_kernel(const int* __restrict__ ei) {
    int e = blockIdx.x * blockDim.x + threadIdx.x;
    if (e < NE) atomicAdd(&g_deg[edge_at(ei, NE + e)], 1);
}
__global__ void reduce_kernel() {
    int b = blockIdx.x, t = threadIdx.x;
    int s = 0;
#pragma unroll
    for (int j = 0; j < 4; j++) {
        int i = b * STILE + t * 4 + j;
        if (i < NN) s += g_deg[i];
    }
#pragma unroll
    for (int o = 16; o; o >>= 1) s += __shfl_down_sync(~0u, s, o);
    __shared__ int ws[8];
    if ((t & 31) == 0) ws[t >> 5] = s;
    __syncthreads();
    if (t == 0) {
        int tot = 0;
#pragma unroll
        for (int w = 0; w < 8; w++) tot += ws[w];
        g_tsum[b] = tot;
    }
}
__global__ void scantop_kernel() {
    if (threadIdx.x == 0) {
        int a = 0;
        for (int i = 0; i < NTILE; i++) { int v = g_tsum[i]; g_tsum[i] = a; a += v; }
    }
}
__global__ void scantile_kernel() {
    int b = blockIdx.x, t = threadIdx.x;
    int v[4], s = 0;
#pragma unroll
    for (int j = 0; j < 4; j++) {
        int i = b * STILE + t * 4 + j;
        int x = (i < NN) ? g_deg[i] : 0;
        s += x; v[j] = s;
    }
    __shared__ int ss[256];
    ss[t] = s;
    __syncthreads();
    for (int o = 1; o < 256; o <<= 1) {
        int x = (t >= o) ? ss[t - o] : 0;
        __syncthreads();
        ss[t] += x;
        __syncthreads();
    }
    int excl = ss[t] - s + g_tsum[b];
#pragma unroll
    for (int j = 0; j < 4; j++) {
        int i = b * STILE + t * 4 + j;
        if (i < NN) g_rowptr[i + 1] = excl + v[j];
    }
    if (b == 0 && t == 0) g_rowptr[0] = 0;
}
__global__ void fill_kernel(const int* __restrict__ ei) {
    int e = blockIdx.x * blockDim.x + threadIdx.x;
    if (e < NE) {
        int src = edge_at(ei, e);
        int dst = edge_at(ei, NE + e);
        int pos = g_rowptr[dst] + atomicAdd(&g_cursor[dst], 1);
        g_col[pos] = src;
    }
}

// ---------------- weight conversion (transpose + hi/lo split) ----------------
__global__ void wconv_kernel(const float* __restrict__ W1, const float* __restrict__ W2) {
    int t = blockIdx.x * blockDim.x + threadIdx.x;
    const int C1 = NL * 256 * 128;
    if (t < C1) {
        int l = t / 32768, rem = t % 32768;
        int n = rem / 128, k = rem % 128;
        float w = W1[l * 32768 + k * 256 + n];
        __nv_bfloat16 h = __float2bfloat16(w);
        g_w1h[t] = h;
        g_w1l[t] = __float2bfloat16(w - __bfloat162float(h));
    } else if (t < 2 * C1) {
        int u = t - C1;
        int l = u / 32768, rem = u % 32768;
        int n = rem / 256, k = rem % 256;
        float w = W2[l * 32768 + k * 128 + n];
        __nv_bfloat16 h = __float2bfloat16(w);
        g_w2h[u] = h;
        g_w2l[u] = __float2bfloat16(w - __bfloat162float(h));
    }
}

// ---------------- aggregation ----------------
__global__ __launch_bounds__(256) void aggregate_kernel(const float* __restrict__ hin) {
    int warp = (blockIdx.x * blockDim.x + threadIdx.x) >> 5;
    int lane = threadIdx.x & 31;
    if (warp >= NN) return;
    const float4* hv = (const float4*)hin;
    float4 acc = __ldg(&hv[warp * 32 + lane]);
    int beg = g_rowptr[warp];
    int end = g_rowptr[warp + 1];
    for (int e = beg; e < end; e++) {
        int s = __ldg(&g_col[e]);
        float4 v = __ldg(&hv[s * 32 + lane]);
        acc.x += v.x; acc.y += v.y; acc.z += v.z; acc.w += v.w;
    }
    ((float4*)g_z)[warp * 32 + lane] = acc;
}

// ---------------- fused HMMA MLP ----------------
// CTA tile = 64 nodes, 256 threads (8 warps = 2 row-groups x 4 col-groups).
// Padded smem rows (+16B) rotate banks by 4 per row -> conflict-free frags.
#define ASTR 136   // elems per A row (128 + 8 pad)
#define YSTR 264   // elems per Y row (256 + 8 pad)
#define WSTR 136   // elems per W row

#define SB1_OFF 0
#define SB2_OFF 1024
#define AH_OFF  2048
#define AL_OFF  (AH_OFF + 64 * ASTR * 2)           // 2048+17408 = 19456
#define YH_OFF  (AL_OFF + 64 * ASTR * 2)           // 36864
#define YL_OFF  (YH_OFF + 64 * YSTR * 2)           // 70656
#define WH_OFF  (YL_OFF + 64 * YSTR * 2)           // 104448
#define WL_OFF  (WH_OFF + 128 * WSTR * 2)          // 139264
#define SMEM_BYTES (WL_OFF + 128 * WSTR * 2)       // 174080

__device__ __forceinline__ uint32_t ld16x2(const char* smem, int off_bytes) {
    return *(const uint32_t*)(smem + off_bytes);
}

__device__ __forceinline__ void stage_w(const __nv_bfloat16* gh, const __nv_bfloat16* gl,
                                        char* smem, int tid, int src_stride, int kofs) {
    int n = tid >> 1, half = tid & 1;
    const uint4* sh = (const uint4*)(gh + (size_t)n * src_stride + kofs + half * 64);
    const uint4* sl = (const uint4*)(gl + (size_t)n * src_stride + kofs + half * 64);
    char* dh = smem + WH_OFF + n * (WSTR * 2) + half * 128;
    char* dl = smem + WL_OFF + n * (WSTR * 2) + half * 128;
#pragma unroll
    for (int j = 0; j < 8; j++) {
        *(uint4*)(dh + j * 16) = __ldg(&sh[j]);
        *(uint4*)(dl + j * 16) = __ldg(&sl[j]);
    }
}

__global__ __launch_bounds__(256, 1) void mlp_mma_kernel(
    const float* __restrict__ b1g, const float* __restrict__ b2g,
    const __nv_bfloat16* __restrict__ w1h, const __nv_bfloat16* __restrict__ w1l,
    const __nv_bfloat16* __restrict__ w2h, const __nv_bfloat16* __restrict__ w2l,
    float* __restrict__ out, int do_relu)
{
    extern __shared__ char smem[];
    int tid = threadIdx.x, lane = tid & 31, wid = tid >> 5;
    int rg = wid & 1;        // row group (32 rows)
    int cg = wid >> 1;       // col group (32 cols)
    int row0 = blockIdx.x * 64;
    float* sb1 = (float*)(smem + SB1_OFF);
    float* sb2 = (float*)(smem + SB2_OFF);

    sb1[tid] = __ldg(&b1g[tid]);
    if (tid < 128) sb2[tid] = __ldg(&b2g[tid]);

    // ---- load z tile (64x128 fp32), split to bf16 hi/lo ----
    {
        int row = tid >> 2, seg = tid & 3;
        int gr = row0 + row;
        char* dh = smem + AH_OFF + row * (ASTR * 2) + seg * 64;   // seg*32 elems
        char* dl = smem + AL_OFF + row * (ASTR * 2) + seg * 64;
        if (gr < NN) {
            const float4* zg = (const float4*)g_z + (size_t)gr * 32 + seg * 8;
#pragma unroll
            for (int j = 0; j < 8; j++) {
                float4 a = __ldg(&zg[j]);
                uint32_t h0, l0, h1, l1;
                split2(a.x, a.y, h0, l0);
                split2(a.z, a.w, h1, l1);
                *(uint32_t*)(dh + j * 8)     = h0;
                *(uint32_t*)(dh + j * 8 + 4) = h1;
                *(uint32_t*)(dl + j * 8)     = l0;
                *(uint32_t*)(dl + j * 8 + 4) = l1;
            }
        } else {
#pragma unroll
            for (int j = 0; j < 8; j++) {
                *(uint2*)(dh + j * 8) = make_uint2(0, 0);
                *(uint2*)(dl + j * 8) = make_uint2(0, 0);
            }
        }
    }

    int fr = lane >> 2;          // fragment row offset 0..7
    int fk = (lane & 3) * 2;     // fragment k offset (elems)

    // ---- GEMM1: C1[64x256] = A @ W1 (two n-halves) + bias + leaky -> Y ----
    for (int nh = 0; nh < 2; nh++) {
        __syncthreads();
        stage_w(w1h + nh * 128 * 128, w1l + nh * 128 * 128, smem, tid, 128, 0);
        __syncthreads();

        float acc[2][4][4];
#pragma unroll
        for (int s = 0; s < 2; s++)
#pragma unroll
            for (int nt = 0; nt < 4; nt++)
#pragma unroll
                for (int q = 0; q < 4; q++) acc[s][nt][q] = 0.f;

#pragma unroll
        for (int ks = 0; ks < 8; ks++) {
            int k0 = ks * 16 + fk;
            uint32_t ah[2][4], al[2][4];
#pragma unroll
            for (int s = 0; s < 2; s++) {
                int r = rg * 32 + s * 16 + fr;
                int base = r * (ASTR * 2) + k0 * 2;
                ah[s][0] = ld16x2(smem + AH_OFF, base);
                ah[s][1] = ld16x2(smem + AH_OFF, base + 8 * (ASTR * 2));
                ah[s][2] = ld16x2(smem + AH_OFF, base + 16);
                ah[s][3] = ld16x2(smem + AH_OFF, base + 8 * (ASTR * 2) + 16);
                al[s][0] = ld16x2(smem + AL_OFF, base);
                al[s][1] = ld16x2(smem + AL_OFF, base + 8 * (ASTR * 2));
                al[s][2] = ld16x2(smem + AL_OFF, base + 16);
                al[s][3] = ld16x2(smem + AL_OFF, base + 8 * (ASTR * 2) + 16);
            }
#pragma unroll
            for (int nt = 0; nt < 4; nt++) {
                int n = cg * 32 + nt * 8 + fr;
                int wb = n * (WSTR * 2) + k0 * 2;
                uint32_t bh[2] = { ld16x2(smem + WH_OFF, wb), ld16x2(smem + WH_OFF, wb + 16) };
                uint32_t bl[2] = { ld16x2(smem + WL_OFF, wb), ld16x2(smem + WL_OFF, wb + 16) };
#pragma unroll
                for (int s = 0; s < 2; s++) {
                    mma16816(acc[s][nt], ah[s], bh);
                    mma16816(acc[s][nt], ah[s], bl);
                    mma16816(acc[s][nt], al[s], bh);
                }
            }
        }

        // epilogue 1: bias + leaky, split -> Y
#pragma unroll
        for (int s = 0; s < 2; s++) {
            int r = rg * 32 + s * 16 + fr;
#pragma unroll
            for (int nt = 0; nt < 4; nt++) {
                int cgl = nh * 128 + cg * 32 + nt * 8 + fk;
                float bA = sb1[cgl], bB = sb1[cgl + 1];
                uint32_t hw, lw;
                float v0 = leaky(acc[s][nt][0] + bA);
                float v1 = leaky(acc[s][nt][1] + bB);
                split2(v0, v1, hw, lw);
                *(uint32_t*)(smem + YH_OFF + r * (YSTR * 2) + cgl * 2) = hw;
                *(uint32_t*)(smem + YL_OFF + r * (YSTR * 2) + cgl * 2) = lw;
                v0 = leaky(acc[s][nt][2] + bA);
                v1 = leaky(acc[s][nt][3] + bB);
                split2(v0, v1, hw, lw);
                *(uint32_t*)(smem + YH_OFF + (r + 8) * (YSTR * 2) + cgl * 2) = hw;
                *(uint32_t*)(smem + YL_OFF + (r + 8) * (YSTR * 2) + cgl * 2) = lw;
            }
        }
    }

    // ---- GEMM2: C2[64x128] = Y @ W2 (two k-halves) ----
    float acc2[2][4][4];
#pragma unroll
    for (int s = 0; s < 2; s++)
#pragma unroll
        for (int nt = 0; nt < 4; nt++)
#pragma unroll
            for (int q = 0; q < 4; q++) acc2[s][nt][q] = 0.f;

    for (int kp = 0; kp < 2; kp++) {
        __syncthreads();
        stage_w(w2h, w2l, smem, tid, 256, kp * 128);
        __syncthreads();

#pragma unroll
        for (int ks = 0; ks < 8; ks++) {
            int k0 = ks * 16 + fk;          // local k in staged W
            int ky = kp * 128 + k0;         // global k in Y
            uint32_t ah[2][4], al[2][4];
#pragma unroll
            for (int s = 0; s < 2; s++) {
                int r = rg * 32 + s * 16 + fr;
                int base = r * (YSTR * 2) + ky * 2;
                ah[s][0] = ld16x2(smem + YH_OFF, base);
                ah[s][1] = ld16x2(smem + YH_OFF, base + 8 * (YSTR * 2));
                ah[s][2] = ld16x2(smem + YH_OFF, base + 16);
                ah[s][3] = ld16x2(smem + YH_OFF, base + 8 * (YSTR * 2) + 16);
                al[s][0] = ld16x2(smem + YL_OFF, base);
                al[s][1] = ld16x2(smem + YL_OFF, base + 8 * (YSTR * 2));
                al[s][2] = ld16x2(smem + YL_OFF, base + 16);
                al[s][3] = ld16x2(smem + YL_OFF, base + 8 * (YSTR * 2) + 16);
            }
#pragma unroll
            for (int nt = 0; nt < 4; nt++) {
                int n = cg * 32 + nt * 8 + fr;
                int wb = n * (WSTR * 2) + k0 * 2;
                uint32_t bh[2] = { ld16x2(smem + WH_OFF, wb), ld16x2(smem + WH_OFF, wb + 16) };
                uint32_t bl[2] = { ld16x2(smem + WL_OFF, wb), ld16x2(smem + WL_OFF, wb + 16) };
#pragma unroll
                for (int s = 0; s < 2; s++) {
                    mma16816(acc2[s][nt], ah[s], bh);
                    mma16816(acc2[s][nt], ah[s], bl);
                    mma16816(acc2[s][nt], al[s], bh);
                }
            }
        }
    }

    // ---- epilogue 2: bias [+ leaky] -> global fp32 ----
#pragma unroll
    for (int s = 0; s < 2; s++) {
        int r = rg * 32 + s * 16 + fr;
#pragma unroll
        for (int nt = 0; nt < 4; nt++) {
            int c = cg * 32 + nt * 8 + fk;
            float bA = sb2[c], bB = sb2[c + 1];
            int node = row0 + r;
            if (node < NN) {
                float v0 = acc2[s][nt][0] + bA;
                float v1 = acc2[s][nt][1] + bB;
                if (do_relu) { v0 = leaky(v0); v1 = leaky(v1); }
                *(float2*)(out + (size_t)node * DD + c) = make_float2(v0, v1);
            }
            if (node + 8 < NN) {
                float v0 = acc2[s][nt][2] + bA;
                float v1 = acc2[s][nt][3] + bB;
                if (do_relu) { v0 = leaky(v0); v1 = leaky(v1); }
                *(float2*)(out + (size_t)(node + 8) * DD + c) = make_float2(v0, v1);
            }
        }
    }
}

// ---------------- launch ----------------
extern "C" void kernel_launch(void* const* d_in, const int* in_sizes, int n_in,
                              void* d_out, int out_size) {
    const float* x  = (const float*)d_in[0];
    const int*   ei = (const int*)d_in[1];
    const float* W1 = (const float*)d_in[2];
    const float* b1 = (const float*)d_in[3];
    const float* W2 = (const float*)d_in[4];
    const float* b2 = (const float*)d_in[5];
    float* out = (float*)d_out;

    float *h0p, *h1p;
    cudaGetSymbolAddress((void**)&h0p, g_h0);
    cudaGetSymbolAddress((void**)&h1p, g_h1);
    __nv_bfloat16 *w1hp, *w1lp, *w2hp, *w2lp;
    cudaGetSymbolAddress((void**)&w1hp, g_w1h);
    cudaGetSymbolAddress((void**)&w1lp, g_w1l);
    cudaGetSymbolAddress((void**)&w2hp, g_w2h);
    cudaGetSymbolAddress((void**)&w2lp, g_w2l);

    cudaFuncSetAttribute(mlp_mma_kernel, cudaFuncAttributeMaxDynamicSharedMemorySize, SMEM_BYTES);

    detect_kernel<<<1, 32>>>(ei);
    zero_kernel<<<(NN + 1023) / 1024, 1024>>>();
    hist_kernel<<<(NE + 255) / 256, 256>>>(ei);
    reduce_kernel<<<NTILE, 256>>>();
    scantop_kernel<<<1, 32>>>();
    scantile_kernel<<<NTILE, 256>>>();
    fill_kernel<<<(NE + 255) / 256, 256>>>(ei);
    wconv_kernel<<<(2 * NL * 256 * 128 + 255) / 256, 256>>>(W1, W2);

    const float* hin = x;
    float* bufs[2] = { h0p, h1p };
    for (int l = 0; l < NL; l++) {
        aggregate_kernel<<<(NN * 32 + 255) / 256, 256>>>(hin);
        float* ho = (l == NL - 1) ? out : bufs[l & 1];
        mlp_mma_kernel<<<(NN + 63) / 64, 256, SMEM_BYTES>>>(
            b1 + (size_t)l * 2 * DD,
            b2 + (size_t)l * DD,
            w1hp + (size_t)l * 256 * 128, w1lp + (size_t)l * 256 * 128,
            w2hp + (size_t)l * 128 * 256, w2lp + (size_t)l * 128 * 256,
            ho, (l < NL - 1) ? 1 : 0);
        hin = ho;
    }
}